// round 4
// baseline (speedup 1.0000x reference)
#include <cuda_runtime.h>
#include <math.h>

#define T_  512
#define B_  2048
#define I_  24
#define H_  20

// Scratch: xg[t][b][u] = float4(i,f,g,o). Padded by one timestep so the
// recurrence prefetch at t+1 == mylen (<= 512) is always in-bounds.
__device__ float4 g_xg[(size_t)(T_ + 1) * B_ * H_];

__device__ __forceinline__ float tanhx(float x) {
    float r; asm("tanh.approx.f32 %0,%1;" : "=f"(r) : "f"(x)); return r;
}
__device__ __forceinline__ float sigx(float x) {   // sigmoid via HW tanh
    return fmaf(0.5f, tanhx(0.5f * x), 0.5f);
}

// ---------------------------------------------------------------------------
// Kernel 1: xg = x @ W_ih^T + (b_ih + b_hh), only where t < len[b].
// Block = one (t, quarter-of-B) tile: 512 b-values, 160 threads
// (8 b-lanes x 20 units), 64 chunks of 8. No shared memory, no barriers:
// x rows come via LDG.128 with L1 broadcast (20 threads share a row).
// Lengths are sorted descending, so len[base] bounds every b in a chunk.
// ---------------------------------------------------------------------------
__global__ __launch_bounds__(160, 2)
void xg_kernel(const float* __restrict__ x,
               const int*   __restrict__ lens,
               const float* __restrict__ Wih,
               const float* __restrict__ bih,
               const float* __restrict__ bhh)
{
    const int t  = blockIdx.x >> 2;
    const int qb = (blockIdx.x & 3) * 512;          // first b of this block
    if (t >= lens[qb]) return;                      // whole tile masked

    const int tid = threadIdx.x;
    const int j   = tid / H_;                       // b-lane 0..7
    const int u   = tid % H_;                       // unit 0..19

    // Per-unit W_ih rows (i,f,g,o) in registers: 96 floats
    float w0[I_], w1[I_], w2[I_], w3[I_];
    #pragma unroll
    for (int k = 0; k < I_; k++) {
        w0[k] = Wih[(0*H_ + u) * I_ + k];
        w1[k] = Wih[(1*H_ + u) * I_ + k];
        w2[k] = Wih[(2*H_ + u) * I_ + k];
        w3[k] = Wih[(3*H_ + u) * I_ + k];
    }
    float4 bias;
    bias.x = bih[0*H_ + u] + bhh[0*H_ + u];
    bias.y = bih[1*H_ + u] + bhh[1*H_ + u];
    bias.z = bih[2*H_ + u] + bhh[2*H_ + u];
    bias.w = bih[3*H_ + u] + bhh[3*H_ + u];

    for (int c = 0; c < 64; c++) {
        const int base = qb + c * 8;
        if (t >= lens[base]) break;                 // rest of tile masked
        const int b = base + j;

        const float4* xr = (const float4*)(x + ((size_t)t * B_ + b) * I_);
        float4 xa = xr[0], xb4 = xr[1], xc = xr[2];
        float4 xd = xr[3], xe  = xr[4], xf = xr[5];
        float xv[I_] = { xa.x,xa.y,xa.z,xa.w,  xb4.x,xb4.y,xb4.z,xb4.w,
                         xc.x,xc.y,xc.z,xc.w,  xd.x,xd.y,xd.z,xd.w,
                         xe.x,xe.y,xe.z,xe.w,  xf.x,xf.y,xf.z,xf.w };

        float4 a = bias;
        #pragma unroll
        for (int k = 0; k < I_; k++) {
            a.x = fmaf(w0[k], xv[k], a.x);
            a.y = fmaf(w1[k], xv[k], a.y);
            a.z = fmaf(w2[k], xv[k], a.z);
            a.w = fmaf(w3[k], xv[k], a.w);
        }
        g_xg[((size_t)t * B_ + b) * H_ + u] = a;
    }
}

// ---------------------------------------------------------------------------
// Kernel 2: fill masked region of out with the constant pads (coalesced in b).
// ---------------------------------------------------------------------------
__global__ __launch_bounds__(256)
void pad_kernel(const int* __restrict__ lens,
                const float* __restrict__ ba,
                const float* __restrict__ bb,
                float* __restrict__ out)
{
    const int idx = blockIdx.x * 256 + threadIdx.x;   // t*B + b
    const int b   = idx & (B_ - 1);
    const int t   = idx >> 11;
    if (t >= lens[b]) {
        const float bav = ba[0], bbv = bb[0];
        out[idx] = __expf(bav);
        out[(size_t)T_ * B_ + idx] =
            fmaxf(bbv, 0.0f) + __logf(1.0f + __expf(-fabsf(bbv)));
    }
}

// ---------------------------------------------------------------------------
// Kernel 3: recurrence, one warp per batch element, runs only t < len[b].
// h broadcast via SHFL, Whh in registers, xg via prefetched LDG.128.
// Lanes 20..31 mirror unit 0 (zero-weighted in the head reduce).
// ---------------------------------------------------------------------------
__global__ __launch_bounds__(128, 4)
void recur_kernel(const int*   __restrict__ lens,
                  const float* __restrict__ Whh,
                  const float* __restrict__ Wa,
                  const float* __restrict__ ba,
                  const float* __restrict__ Wb,
                  const float* __restrict__ bb,
                  float* __restrict__ out)
{
    const int lane = threadIdx.x & 31;
    const int wid  = threadIdx.x >> 5;
    const int b    = blockIdx.x * 4 + wid;
    const int uu   = (lane < H_) ? lane : 0;

    float wi[H_], wf[H_], wg[H_], wo[H_];
    #pragma unroll
    for (int k = 0; k < H_; k++) {
        wi[k] = Whh[(0*H_ + uu) * H_ + k];
        wf[k] = Whh[(1*H_ + uu) * H_ + k];
        wg[k] = Whh[(2*H_ + uu) * H_ + k];
        wo[k] = Whh[(3*H_ + uu) * H_ + k];
    }
    const float wa  = (lane < H_) ? Wa[lane] : 0.0f;
    const float wb  = (lane < H_) ? Wb[lane] : 0.0f;
    const float bav = ba[0], bbv = bb[0];
    const int   mylen = lens[b];          // >= 1 by construction

    float h = 0.0f, c = 0.0f;

    const float4* xp = &g_xg[(size_t)b * H_ + uu];
    const size_t  xstride = (size_t)B_ * H_;

    float4 xg = *xp;                      // t = 0
    xp += xstride;

    float* outA = out + b;
    float* outB = out + (size_t)T_ * B_ + b;

    for (int t = 0; t < mylen; t++) {
        float4 nxt = *xp;                 // t+1 <= mylen <= 512 (padded)
        xp += xstride;

        float ai = xg.x, af = xg.y, ag = xg.z, ao = xg.w;
        #pragma unroll
        for (int k = 0; k < H_; k++) {
            float hk = __shfl_sync(0xffffffffu, h, k);
            ai = fmaf(wi[k], hk, ai);
            af = fmaf(wf[k], hk, af);
            ag = fmaf(wg[k], hk, ag);
            ao = fmaf(wo[k], hk, ao);
        }

        c = fmaf(sigx(af), c, sigx(ai) * tanhx(ag));
        h = sigx(ao) * tanhx(c);

        float za = h * wa, zb = h * wb;
        #pragma unroll
        for (int off = 16; off >= 1; off >>= 1) {
            za += __shfl_xor_sync(0xffffffffu, za, off);
            zb += __shfl_xor_sync(0xffffffffu, zb, off);
        }
        if (lane == 0) {
            outA[(size_t)t * B_] = __expf(za + bav);
        } else if (lane == 1) {
            float z = zb + bbv;
            outB[(size_t)t * B_] =
                fmaxf(z, 0.0f) + __logf(1.0f + __expf(-fabsf(z)));
        }
        xg = nxt;
    }
}

extern "C" void kernel_launch(void* const* d_in, const int* in_sizes, int n_in,
                              void* d_out, int out_size)
{
    const float *x = 0, *Wih = 0, *Whh = 0, *bih = 0, *bhh = 0;
    const float *Wa = 0, *ba = 0, *Wb = 0, *bb = 0;
    const int *lens = 0;
    int seen80 = 0, seen20 = 0, seen1 = 0;
    for (int i = 0; i < n_in; i++) {
        int s = in_sizes[i];
        if      (s == T_ * B_ * I_) x    = (const float*)d_in[i];
        else if (s == B_)           lens = (const int*)d_in[i];
        else if (s == 4*H_ * I_)    Wih  = (const float*)d_in[i];
        else if (s == 4*H_ * H_)    Whh  = (const float*)d_in[i];
        else if (s == 4*H_) { if (seen80++ == 0) bih = (const float*)d_in[i]; else bhh = (const float*)d_in[i]; }
        else if (s == H_)   { if (seen20++ == 0) Wa  = (const float*)d_in[i]; else Wb  = (const float*)d_in[i]; }
        else if (s == 1)    { if (seen1++  == 0) ba  = (const float*)d_in[i]; else bb  = (const float*)d_in[i]; }
    }

    float* out = (float*)d_out;
    xg_kernel<<<T_ * 4, 160>>>(x, lens, Wih, bih, bhh);
    pad_kernel<<<(T_ * B_) / 256, 256>>>(lens, ba, bb, out);
    recur_kernel<<<B_ / 4, 128>>>(lens, Whh, Wa, ba, Wb, bb, out);
}

// round 5
// speedup vs baseline: 1.3536x; 1.3536x over previous
#include <cuda_runtime.h>
#include <math.h>

#define T_  512
#define B_  2048
#define I_  24
#define H_  20

// xg[t][b][u] = float4(i,f,g,o). One pad timestep for the recur prefetch.
__device__ float4 g_xg[(size_t)(T_ + 1) * B_ * H_];
// h[t*B+b][u] for the head pass.
__device__ float  g_h[(size_t)T_ * B_ * H_];

__device__ __forceinline__ float tanhx(float x) {
    float r; asm("tanh.approx.f32 %0,%1;" : "=f"(r) : "f"(x)); return r;
}
__device__ __forceinline__ float sigx(float x) {   // sigmoid via HW tanh
    return fmaf(0.5f, tanhx(0.5f * x), 0.5f);
}

// ---------------------------------------------------------------------------
// Kernel 1: xg = x @ W_ih^T + (b_ih+b_hh) for t < len[b].
// One token per thread. Weights staged in shared, transposed to
// wsh[group][k][r] with r = 4*u_local + gate so LDS.128 feeds float4 accs
// that store directly in the recur-friendly [t][b][u](i,f,g,o) layout.
// Block = 128 consecutive b at fixed t; sorted lengths => active prefix.
// ---------------------------------------------------------------------------
#define XG_TPB 128
__global__ __launch_bounds__(XG_TPB)
void xg_kernel(const float* __restrict__ x,
               const int*   __restrict__ lens,
               const float* __restrict__ Wih,
               const float* __restrict__ bih,
               const float* __restrict__ bhh)
{
    __shared__ float wsh[4][I_][20];   // [unit-group][k][4*ul+gate]
    __shared__ float bsh[4][20];

    const int t  = blockIdx.x >> 4;               // 16 blocks per t
    const int b0 = (blockIdx.x & 15) * XG_TPB;
    if (t >= lens[b0]) return;                    // whole block masked

    const int tid = threadIdx.x;
    for (int idx = tid; idx < 4 * I_ * 20; idx += XG_TPB) {
        int r = idx % 20, k = (idx / 20) % I_, grp = idx / (20 * I_);
        int u = grp * 5 + (r >> 2), gate = r & 3;
        wsh[grp][k][r] = Wih[(gate * H_ + u) * I_ + k];
    }
    if (tid < 80) {
        int r = tid % 20, grp = tid / 20;
        int u = grp * 5 + (r >> 2), gate = r & 3;
        bsh[grp][r] = bih[gate * H_ + u] + bhh[gate * H_ + u];
    }
    __syncthreads();

    const int b = b0 + tid;
    if (t >= lens[b]) return;                     // masked tail threads

    float xr[I_];
    const float4* xp = (const float4*)(x + ((size_t)t * B_ + b) * I_);
    #pragma unroll
    for (int q = 0; q < 6; q++) {
        float4 v = xp[q];
        xr[q*4+0] = v.x; xr[q*4+1] = v.y; xr[q*4+2] = v.z; xr[q*4+3] = v.w;
    }

    float4* outp = &g_xg[((size_t)t * B_ + b) * H_];
    #pragma unroll
    for (int grp = 0; grp < 4; grp++) {
        float4 a[5];
        const float4* bq = (const float4*)bsh[grp];
        #pragma unroll
        for (int j = 0; j < 5; j++) a[j] = bq[j];

        #pragma unroll 8
        for (int k = 0; k < I_; k++) {
            const float xk = xr[k];
            const float4* wp = (const float4*)&wsh[grp][k][0];
            #pragma unroll
            for (int j = 0; j < 5; j++) {
                float4 w = wp[j];
                a[j].x = fmaf(w.x, xk, a[j].x);
                a[j].y = fmaf(w.y, xk, a[j].y);
                a[j].z = fmaf(w.z, xk, a[j].z);
                a[j].w = fmaf(w.w, xk, a[j].w);
            }
        }
        #pragma unroll
        for (int j = 0; j < 5; j++) outp[grp * 5 + j] = a[j];
    }
}

// ---------------------------------------------------------------------------
// Kernel 2: recurrence, one warp per batch element, t < len[b] only.
// h broadcast via SHFL, Whh in registers, xg via prefetched LDG.128.
// Heads offloaded: h stored to g_h (80B contiguous per warp-step).
// ---------------------------------------------------------------------------
__global__ __launch_bounds__(128, 4)
void recur_kernel(const int*   __restrict__ lens,
                  const float* __restrict__ Whh)
{
    const int lane = threadIdx.x & 31;
    const int wid  = threadIdx.x >> 5;
    const int b    = blockIdx.x * 4 + wid;
    const int uu   = (lane < H_) ? lane : 0;      // lanes 20..31 mirror u=0

    float wi[H_], wf[H_], wg[H_], wo[H_];
    #pragma unroll
    for (int k = 0; k < H_; k++) {
        wi[k] = Whh[(0*H_ + uu) * H_ + k];
        wf[k] = Whh[(1*H_ + uu) * H_ + k];
        wg[k] = Whh[(2*H_ + uu) * H_ + k];
        wo[k] = Whh[(3*H_ + uu) * H_ + k];
    }
    const int mylen = lens[b];                    // >= 1

    float h = 0.0f, c = 0.0f;

    const float4* xp = &g_xg[(size_t)b * H_ + uu];
    const size_t  xstride = (size_t)B_ * H_;
    float4 xg = *xp;                              // t = 0
    xp += xstride;

    float* hp = &g_h[(size_t)b * H_ + lane];

    for (int t = 0; t < mylen; t++) {
        float4 nxt = *xp;                         // row t+1 <= 512 (padded)
        xp += xstride;

        float ai = xg.x, af = xg.y, ag = xg.z, ao = xg.w;
        #pragma unroll
        for (int k = 0; k < H_; k++) {
            float hk = __shfl_sync(0xffffffffu, h, k);
            ai = fmaf(wi[k], hk, ai);
            af = fmaf(wf[k], hk, af);
            ag = fmaf(wg[k], hk, ag);
            ao = fmaf(wo[k], hk, ao);
        }

        c = fmaf(sigx(af), c, sigx(ai) * tanhx(ag));
        h = sigx(ao) * tanhx(c);

        if (lane < H_) hp[(size_t)t * (B_ * H_)] = h;
        xg = nxt;
    }
}

// ---------------------------------------------------------------------------
// Kernel 3: heads + padding over the full [T, B] grid.
//   t <  len[b]: alpha = exp(h.Wa + ba), beta = softplus(h.Wb + bb)
//   t >= len[b]: h == 0 => constants from the biases.
// ---------------------------------------------------------------------------
__global__ __launch_bounds__(256)
void head_kernel(const int*   __restrict__ lens,
                 const float* __restrict__ Wa,
                 const float* __restrict__ ba,
                 const float* __restrict__ Wb,
                 const float* __restrict__ bb,
                 float* __restrict__ out)
{
    const int idx = blockIdx.x * 256 + threadIdx.x;   // t*B + b
    const int b   = idx & (B_ - 1);
    const int t   = idx >> 11;

    float za = ba[0], zb = bb[0];
    if (t < lens[b]) {
        float4 hq[5];
        const float4* hp = (const float4*)&g_h[(size_t)idx * H_];
        #pragma unroll
        for (int q = 0; q < 5; q++) hq[q] = hp[q];
        const float* hv = (const float*)hq;
        #pragma unroll
        for (int k = 0; k < H_; k++) {
            za = fmaf(hv[k], Wa[k], za);
            zb = fmaf(hv[k], Wb[k], zb);
        }
    }
    out[idx] = __expf(za);
    out[(size_t)T_ * B_ + idx] =
        fmaxf(zb, 0.0f) + __logf(1.0f + __expf(-fabsf(zb)));
}

extern "C" void kernel_launch(void* const* d_in, const int* in_sizes, int n_in,
                              void* d_out, int out_size)
{
    const float *x = 0, *Wih = 0, *Whh = 0, *bih = 0, *bhh = 0;
    const float *Wa = 0, *ba = 0, *Wb = 0, *bb = 0;
    const int *lens = 0;
    int seen80 = 0, seen20 = 0, seen1 = 0;
    for (int i = 0; i < n_in; i++) {
        int s = in_sizes[i];
        if      (s == T_ * B_ * I_) x    = (const float*)d_in[i];
        else if (s == B_)           lens = (const int*)d_in[i];
        else if (s == 4*H_ * I_)    Wih  = (const float*)d_in[i];
        else if (s == 4*H_ * H_)    Whh  = (const float*)d_in[i];
        else if (s == 4*H_) { if (seen80++ == 0) bih = (const float*)d_in[i]; else bhh = (const float*)d_in[i]; }
        else if (s == H_)   { if (seen20++ == 0) Wa  = (const float*)d_in[i]; else Wb  = (const float*)d_in[i]; }
        else if (s == 1)    { if (seen1++  == 0) ba  = (const float*)d_in[i]; else bb  = (const float*)d_in[i]; }
    }

    float* out = (float*)d_out;
    xg_kernel<<<T_ * (B_ / XG_TPB), XG_TPB>>>(x, lens, Wih, bih, bhh);
    recur_kernel<<<B_ / 4, 128>>>(lens, Whh);
    head_kernel<<<(T_ * B_) / 256, 256>>>(lens, Wa, ba, Wb, bb, out);
}

// round 6
// speedup vs baseline: 1.3740x; 1.0151x over previous
#include <cuda_runtime.h>
#include <math.h>

#define T_  512
#define B_  2048
#define I_  24
#define H_  20

// xg[t][b][u] = float4(i,f,g,o). One pad timestep for the recur prefetch.
__device__ float4 g_xg[(size_t)(T_ + 1) * B_ * H_];
// h[t*B+b][u] for the head pass.
__device__ float  g_h[(size_t)T_ * B_ * H_];

__device__ __forceinline__ float tanhx(float x) {
    float r; asm("tanh.approx.f32 %0,%1;" : "=f"(r) : "f"(x)); return r;
}
__device__ __forceinline__ float sigx(float x) {   // sigmoid via HW tanh
    return fmaf(0.5f, tanhx(0.5f * x), 0.5f);
}

// ---------------------------------------------------------------------------
// Kernel 1: xg = x @ W_ih^T + (b_ih+b_hh) for t < len[b].
// TWO tokens per thread (b0+tid, b0+tid+128): each broadcast LDS.128 of
// weights feeds 8 FMAs, halving L1TEX pressure vs 1-token (was the
// bottleneck: L1=83%). Weights staged in shared transposed to
// wsh[grp][k][4*ul+gate] so float4 accumulators store directly in the
// recur layout. Sorted lengths => act(second token) implies act(first).
// ---------------------------------------------------------------------------
#define XG_TPB 128
__global__ __launch_bounds__(XG_TPB, 3)
void xg_kernel(const float* __restrict__ x,
               const int*   __restrict__ lens,
               const float* __restrict__ Wih,
               const float* __restrict__ bih,
               const float* __restrict__ bhh)
{
    __shared__ float wsh[4][I_][20];   // [unit-group][k][4*ul+gate]
    __shared__ float bsh[4][20];

    const int t  = blockIdx.x >> 3;               // 8 chunks of 256 b per t
    const int b0 = (blockIdx.x & 7) * 256;
    if (t >= lens[b0]) return;                    // whole chunk masked

    const int tid = threadIdx.x;
    for (int idx = tid; idx < 4 * I_ * 20; idx += XG_TPB) {
        int r = idx % 20, k = (idx / 20) % I_, grp = idx / (20 * I_);
        int u = grp * 5 + (r >> 2), gate = r & 3;
        wsh[grp][k][r] = Wih[(gate * H_ + u) * I_ + k];
    }
    if (tid < 80) {
        int r = tid % 20, grp = tid / 20;
        int u = grp * 5 + (r >> 2), gate = r & 3;
        bsh[grp][r] = bih[gate * H_ + u] + bhh[gate * H_ + u];
    }
    __syncthreads();

    const int bA = b0 + tid;
    const int bB = bA + 128;
    const bool actA = (t < lens[bA]);             // actB => actA (sorted desc)
    const bool actB = (t < lens[bB]);
    if (!actA) return;                            // no barriers after this

    // Load both tokens' x (always in-bounds; store is what's predicated).
    float xA[I_], xB[I_];
    {
        const float4* pA = (const float4*)(x + ((size_t)t * B_ + bA) * I_);
        const float4* pB = (const float4*)(x + ((size_t)t * B_ + bB) * I_);
        #pragma unroll
        for (int q = 0; q < 6; q++) {
            float4 v = pA[q];
            xA[q*4+0]=v.x; xA[q*4+1]=v.y; xA[q*4+2]=v.z; xA[q*4+3]=v.w;
            float4 w = pB[q];
            xB[q*4+0]=w.x; xB[q*4+1]=w.y; xB[q*4+2]=w.z; xB[q*4+3]=w.w;
        }
    }

    float4* outA = &g_xg[((size_t)t * B_ + bA) * H_];
    float4* outB = &g_xg[((size_t)t * B_ + bB) * H_];

    #pragma unroll 1
    for (int grp = 0; grp < 4; grp++) {
        float4 a[5], b4[5];
        const float4* bq = (const float4*)bsh[grp];
        #pragma unroll
        for (int j = 0; j < 5; j++) { a[j] = bq[j]; b4[j] = bq[j]; }

        #pragma unroll 8
        for (int k = 0; k < I_; k++) {
            const float ka = xA[k], kb = xB[k];
            const float4* wp = (const float4*)&wsh[grp][k][0];
            #pragma unroll
            for (int j = 0; j < 5; j++) {
                float4 w = wp[j];
                a[j].x  = fmaf(w.x, ka, a[j].x);
                a[j].y  = fmaf(w.y, ka, a[j].y);
                a[j].z  = fmaf(w.z, ka, a[j].z);
                a[j].w  = fmaf(w.w, ka, a[j].w);
                b4[j].x = fmaf(w.x, kb, b4[j].x);
                b4[j].y = fmaf(w.y, kb, b4[j].y);
                b4[j].z = fmaf(w.z, kb, b4[j].z);
                b4[j].w = fmaf(w.w, kb, b4[j].w);
            }
        }
        #pragma unroll
        for (int j = 0; j < 5; j++) {
            outA[grp * 5 + j] = a[j];
            if (actB) outB[grp * 5 + j] = b4[j];
        }
    }
}

// ---------------------------------------------------------------------------
// Kernel 2: recurrence, one warp per batch element, t < len[b] only.
// Length-balanced warp->b mapping: block j takes {2j, 2j+1, 2047-2j, 2046-2j}
// so long and short sequences share a block (sorted-desc lengths).
// h broadcast via SHFL, Whh in registers, xg via prefetched LDG.128.
// ---------------------------------------------------------------------------
__global__ __launch_bounds__(128, 4)
void recur_kernel(const int*   __restrict__ lens,
                  const float* __restrict__ Whh)
{
    const int lane = threadIdx.x & 31;
    const int wid  = threadIdx.x >> 5;
    const int j    = blockIdx.x;
    const int b    = (wid < 2) ? (2*j + wid) : (2047 - 2*j - (wid - 2));
    const int uu   = (lane < H_) ? lane : 0;      // lanes 20..31 mirror u=0

    float wi[H_], wf[H_], wg[H_], wo[H_];
    #pragma unroll
    for (int k = 0; k < H_; k++) {
        wi[k] = Whh[(0*H_ + uu) * H_ + k];
        wf[k] = Whh[(1*H_ + uu) * H_ + k];
        wg[k] = Whh[(2*H_ + uu) * H_ + k];
        wo[k] = Whh[(3*H_ + uu) * H_ + k];
    }
    const int mylen = lens[b];                    // >= 1

    float h = 0.0f, c = 0.0f;

    const float4* xp = &g_xg[(size_t)b * H_ + uu];
    const size_t  xstride = (size_t)B_ * H_;
    float4 xg = *xp;                              // t = 0
    xp += xstride;

    float* hp = &g_h[(size_t)b * H_ + lane];

    for (int t = 0; t < mylen; t++) {
        float4 nxt = *xp;                         // row t+1 <= 512 (padded)
        xp += xstride;

        float ai = xg.x, af = xg.y, ag = xg.z, ao = xg.w;
        #pragma unroll
        for (int k = 0; k < H_; k++) {
            float hk = __shfl_sync(0xffffffffu, h, k);
            ai = fmaf(wi[k], hk, ai);
            af = fmaf(wf[k], hk, af);
            ag = fmaf(wg[k], hk, ag);
            ao = fmaf(wo[k], hk, ao);
        }

        c = fmaf(sigx(af), c, sigx(ai) * tanhx(ag));
        h = sigx(ao) * tanhx(c);

        if (lane < H_) hp[(size_t)t * (B_ * H_)] = h;
        xg = nxt;
    }
}

// ---------------------------------------------------------------------------
// Kernel 3: heads + padding over the full [T, B] grid.
// ---------------------------------------------------------------------------
__global__ __launch_bounds__(256)
void head_kernel(const int*   __restrict__ lens,
                 const float* __restrict__ Wa,
                 const float* __restrict__ ba,
                 const float* __restrict__ Wb,
                 const float* __restrict__ bb,
                 float* __restrict__ out)
{
    const int idx = blockIdx.x * 256 + threadIdx.x;   // t*B + b
    const int b   = idx & (B_ - 1);
    const int t   = idx >> 11;

    float za = ba[0], zb = bb[0];
    if (t < lens[b]) {
        float4 hq[5];
        const float4* hp = (const float4*)&g_h[(size_t)idx * H_];
        #pragma unroll
        for (int q = 0; q < 5; q++) hq[q] = hp[q];
        const float* hv = (const float*)hq;
        #pragma unroll
        for (int k = 0; k < H_; k++) {
            za = fmaf(hv[k], Wa[k], za);
            zb = fmaf(hv[k], Wb[k], zb);
        }
    }
    out[idx] = __expf(za);
    out[(size_t)T_ * B_ + idx] =
        fmaxf(zb, 0.0f) + __logf(1.0f + __expf(-fabsf(zb)));
}

extern "C" void kernel_launch(void* const* d_in, const int* in_sizes, int n_in,
                              void* d_out, int out_size)
{
    const float *x = 0, *Wih = 0, *Whh = 0, *bih = 0, *bhh = 0;
    const float *Wa = 0, *ba = 0, *Wb = 0, *bb = 0;
    const int *lens = 0;
    int seen80 = 0, seen20 = 0, seen1 = 0;
    for (int i = 0; i < n_in; i++) {
        int s = in_sizes[i];
        if      (s == T_ * B_ * I_) x    = (const float*)d_in[i];
        else if (s == B_)           lens = (const int*)d_in[i];
        else if (s == 4*H_ * I_)    Wih  = (const float*)d_in[i];
        else if (s == 4*H_ * H_)    Whh  = (const float*)d_in[i];
        else if (s == 4*H_) { if (seen80++ == 0) bih = (const float*)d_in[i]; else bhh = (const float*)d_in[i]; }
        else if (s == H_)   { if (seen20++ == 0) Wa  = (const float*)d_in[i]; else Wb  = (const float*)d_in[i]; }
        else if (s == 1)    { if (seen1++  == 0) ba  = (const float*)d_in[i]; else bb  = (const float*)d_in[i]; }
    }

    float* out = (float*)d_out;
    xg_kernel<<<T_ * 8, XG_TPB>>>(x, lens, Wih, bih, bhh);
    recur_kernel<<<512, 128>>>(lens, Whh);
    head_kernel<<<(T_ * B_) / 256, 256>>>(lens, Wa, ba, Wb, bb, out);
}